// round 6
// baseline (speedup 1.0000x reference)
#include <cuda_runtime.h>

#define ESP 1e-12f
#define C_DIM 8192
#define THREADS 256

__device__ double        g_accum;   // zero-init; reset by finalizer each run
__device__ unsigned int  g_ticket;  // zero-init; reset by finalizer each run

__device__ __forceinline__ float fsqrt_approx(float x) {
    float r;
    asm("sqrt.approx.f32 %0, %1;" : "=f"(r) : "f"(x));
    return r;
}

__global__ void __launch_bounds__(THREADS) mfl_fused_kernel(
    const float* __restrict__ p,
    const float* __restrict__ g,
    float* __restrict__ out,
    int n_rows)
{
    const int row = blockIdx.x;
    const float4* __restrict__ p4 =
        reinterpret_cast<const float4*>(p + (size_t)row * C_DIM);
    const float4* __restrict__ g4 =
        reinterpret_cast<const float4*>(g + (size_t)row * C_DIM);
    const int tid = threadIdx.x;

    // Dual accumulators: halve the serial FADD dependency chain.
    float sum0 = 0.0f, sum1 = 0.0f;
    int   cnt0 = 0,    cnt1 = 0;

    // C_DIM/4 = 2048 float4s, 256 threads -> 8 iterations, streaming loads.
    #pragma unroll
    for (int i = 0; i < 8; i++) {
        float4 pv = __ldcs(&p4[tid + i * THREADS]);
        float4 gv = __ldcs(&g4[tid + i * THREADS]);

        #pragma unroll
        for (int k = 0; k < 4; k++) {
            float pe = (&pv.x)[k];
            float ge = (&gv.x)[k];
            float a = fmaf(pe, ge, ESP);
            float b = fmaf(1.0f - pe, 1.0f - ge, ESP);
            float l = 1.0f - (fsqrt_approx(a) + fsqrt_approx(b));
            bool nz = (ge != 0.0f);
            if (k & 1) {
                sum1 += nz ? l : 0.0f;
                cnt1 += nz ? 1 : 0;
            } else {
                sum0 += nz ? l : 0.0f;
                cnt0 += nz ? 1 : 0;
            }
        }
    }

    float sum = sum0 + sum1;
    int   cnt = cnt0 + cnt1;

    // Warp reduction: REDUX for the int count, shuffles for the float sum.
    cnt = __reduce_add_sync(0xffffffffu, cnt);
    #pragma unroll
    for (int o = 16; o > 0; o >>= 1)
        sum += __shfl_down_sync(0xffffffffu, sum, o);

    __shared__ float s_sum[THREADS / 32];
    __shared__ int   s_cnt[THREADS / 32];
    const int wid = tid >> 5;
    const int lid = tid & 31;
    if (lid == 0) {
        s_sum[wid] = sum;
        s_cnt[wid] = cnt;
    }
    __syncthreads();

    if (tid == 0) {
        float bsum = 0.0f;
        int   bcnt = 0;
        #pragma unroll
        for (int w = 0; w < THREADS / 32; w++) {
            bsum += s_sum[w];
            bcnt += s_cnt[w];
        }
        float row_loss = (bcnt > 0) ? (bsum / (float)bcnt) : 0.0f;

        atomicAdd(&g_accum, (double)row_loss);
        __threadfence();
        unsigned int t = atomicAdd(&g_ticket, 1u);
        if (t == (unsigned int)(gridDim.x - 1)) {
            // Last block: read-and-reset state atomically so every graph
            // replay starts zeroed (matches zero-initialized first call).
            unsigned long long bits =
                atomicExch((unsigned long long*)&g_accum, 0ull);
            atomicExch(&g_ticket, 0u);
            double total = __longlong_as_double((long long)bits);
            out[0] = (float)(total / (double)n_rows);
        }
    }
}

extern "C" void kernel_launch(void* const* d_in, const int* in_sizes, int n_in,
                              void* d_out, int out_size) {
    const float* p = (const float*)d_in[0];
    const float* g = (const float*)d_in[1];
    float* out = (float*)d_out;

    const int total = in_sizes[0];
    const int n_rows = total / C_DIM;   // 16384

    mfl_fused_kernel<<<n_rows, THREADS>>>(p, g, out, n_rows);
}

// round 7
// speedup vs baseline: 1.0694x; 1.0694x over previous
#include <cuda_runtime.h>

#define ESP 1e-12f
#define C_DIM 8192
#define THREADS 256

__device__ double        g_accum;   // zero-init; reset by finalizer each run
__device__ unsigned int  g_ticket;  // zero-init; reset by finalizer each run

__device__ __forceinline__ float fsqrt_approx(float x) {
    float r;
    asm("sqrt.approx.f32 %0, %1;" : "=f"(r) : "f"(x));
    return r;
}

// Pin 8 blocks/SM (regs <= 32): Round-6 showed that +3 regs drops residency
// to 7/SM and costs ~6% DRAM utilization. This bound locks in the R2 layout.
__global__ void __launch_bounds__(THREADS, 8) mfl_fused_kernel(
    const float* __restrict__ p,
    const float* __restrict__ g,
    float* __restrict__ out,
    int n_rows)
{
    const int row = blockIdx.x;
    const float4* __restrict__ p4 =
        reinterpret_cast<const float4*>(p + (size_t)row * C_DIM);
    const float4* __restrict__ g4 =
        reinterpret_cast<const float4*>(g + (size_t)row * C_DIM);
    const int tid = threadIdx.x;

    float sum = 0.0f;
    int   cnt = 0;

    // C_DIM/4 = 2048 float4s, 256 threads -> 8 iterations. Streaming loads:
    // data is touched exactly once, keep it evict-first in L2.
    #pragma unroll
    for (int i = 0; i < 8; i++) {
        float4 pv = __ldcs(&p4[tid + i * THREADS]);
        float4 gv = __ldcs(&g4[tid + i * THREADS]);

        #pragma unroll
        for (int k = 0; k < 4; k++) {
            float pe = (&pv.x)[k];
            float ge = (&gv.x)[k];
            float a = fmaf(pe, ge, ESP);
            float b = fmaf(1.0f - pe, 1.0f - ge, ESP);
            float l = 1.0f - (fsqrt_approx(a) + fsqrt_approx(b));
            bool nz = (ge != 0.0f);
            sum += nz ? l : 0.0f;
            cnt += nz ? 1 : 0;
        }
    }

    // Warp reduction
    #pragma unroll
    for (int o = 16; o > 0; o >>= 1) {
        sum += __shfl_down_sync(0xffffffffu, sum, o);
        cnt += __shfl_down_sync(0xffffffffu, cnt, o);
    }

    __shared__ float s_sum[THREADS / 32];
    __shared__ int   s_cnt[THREADS / 32];
    const int wid = tid >> 5;
    const int lid = tid & 31;
    if (lid == 0) {
        s_sum[wid] = sum;
        s_cnt[wid] = cnt;
    }
    __syncthreads();

    if (tid == 0) {
        float bsum = 0.0f;
        int   bcnt = 0;
        #pragma unroll
        for (int w = 0; w < THREADS / 32; w++) {
            bsum += s_sum[w];
            bcnt += s_cnt[w];
        }
        float row_loss = (bcnt > 0) ? (bsum / (float)bcnt) : 0.0f;

        atomicAdd(&g_accum, (double)row_loss);
        __threadfence();
        unsigned int t = atomicAdd(&g_ticket, 1u);
        if (t == (unsigned int)(gridDim.x - 1)) {
            // Last block: read-and-reset accumulator + ticket atomically so
            // every graph replay starts from zeroed state (matches the
            // zero-initialized first call), then emit the result.
            unsigned long long bits =
                atomicExch((unsigned long long*)&g_accum, 0ull);
            atomicExch(&g_ticket, 0u);
            double total = __longlong_as_double((long long)bits);
            out[0] = (float)(total / (double)n_rows);
        }
    }
}

extern "C" void kernel_launch(void* const* d_in, const int* in_sizes, int n_in,
                              void* d_out, int out_size) {
    const float* p = (const float*)d_in[0];
    const float* g = (const float*)d_in[1];
    float* out = (float*)d_out;

    const int total = in_sizes[0];
    const int n_rows = total / C_DIM;   // 16384

    mfl_fused_kernel<<<n_rows, THREADS>>>(p, g, out, n_rows);
}